// round 2
// baseline (speedup 1.0000x reference)
#include <cuda_runtime.h>
#include <cstdint>

// Problem constants (shapes fixed by the reference; B derived from in_sizes).
#define NIN   64
#define NOUT  64
#define HH    192
#define WW    192
#define HO    190
#define WO    190
#define OG    8            // output channels per block
#define NG    (NOUT / OG)  // 8 output-channel groups
#define MAXK  2048         // capacity for kernel entries (actual K = 1024)
#define WCAP  256          // smem-staged weight entries per block

typedef unsigned long long ull;

// Scratch (static device allocations are allowed; cudaMalloc is not).
// g_start: CSR offsets over bins (og, in_channel, ol)  -> 8*64*8 = 4096 bins + total.
// g_w:     per entry 10 x u64: 9 duplicated (w,w) f32x2 pairs + 1 pad (80B).
// 16B alignment is REQUIRED: the conv inner loop reads these as ulonglong2.
__device__ int g_start[NG * 512 + 1];
__device__ __align__(16) ull g_w[MAXK * 10];

__device__ __forceinline__ ull pk2(float lo, float hi) {
    ull r;
    asm("mov.b64 %0, {%1, %2};" : "=l"(r) : "f"(lo), "f"(hi));
    return r;
}
__device__ __forceinline__ ull fma2(ull a, ull b, ull c) {
    ull d;
    asm("fma.rn.f32x2 %0, %1, %2, %3;" : "=l"(d) : "l"(a), "l"(b), "l"(c));
    return d;
}

// ---------------------------------------------------------------------------
// Prep: bin the K kernels by (out_group, in_channel, out_local), CSR + scatter,
// and write weights as duplicated f32x2 pairs. Single block, 1024 threads.
// ---------------------------------------------------------------------------
__global__ void prep_kernel(const float* __restrict__ w,
                            const int* __restrict__ cin,
                            const int* __restrict__ cout,
                            int K) {
    __shared__ int cnt[4096];
    __shared__ int part[1024];
    int t = threadIdx.x;

    for (int e = t; e < 4096; e += 1024) cnt[e] = 0;
    __syncthreads();

    for (int k = t; k < K; k += 1024) {
        int o = cout[k], i = cin[k];
        int bin = ((o >> 3) << 9) | (i << 3) | (o & 7);
        atomicAdd(&cnt[bin], 1);
    }
    __syncthreads();

    // Blocked scan: each thread owns 4 consecutive bins.
    int c4[4];
    int s = 0;
#pragma unroll
    for (int q = 0; q < 4; q++) { c4[q] = cnt[t * 4 + q]; s += c4[q]; }
    part[t] = s;
    __syncthreads();
    for (int off = 1; off < 1024; off <<= 1) {
        int v = (t >= off) ? part[t - off] : 0;
        __syncthreads();
        part[t] += v;
        __syncthreads();
    }
    int run = part[t] - s;  // exclusive base for this thread's 4 bins
#pragma unroll
    for (int q = 0; q < 4; q++) {
        int bin = t * 4 + q;
        int c = c4[q];
        cnt[bin] = run;           // cursor for scatter
        g_start[bin] = run;       // CSR
        run += c;
    }
    if (t == 1023) g_start[4096] = run;  // total
    __syncthreads();

    for (int k = t; k < K; k += 1024) {
        int o = cout[k], i = cin[k];
        int bin = ((o >> 3) << 9) | (i << 3) | (o & 7);
        int slot = atomicAdd(&cnt[bin], 1);
        if (slot < MAXK) {
            ull* dst = &g_w[(size_t)slot * 10];
#pragma unroll
            for (int q = 0; q < 9; q++) {
                float wv = w[k * 9 + q];
                dst[q] = pk2(wv, wv);
            }
            dst[9] = 0;
        }
    }
}

// ---------------------------------------------------------------------------
// Main conv: one block = (batch b, out-channel group og, 16x64 output tile).
// Loop input channels; patch in smem; accumulate 8 out channels x 4 px/thread
// as packed f32x2 pairs.
// ---------------------------------------------------------------------------
#define CONV_INNER(WRPTR)                                                     \
    do {                                                                      \
        const ulonglong2* wr = (const ulonglong2*)(WRPTR);                    \
        ulonglong2 q0 = wr[0], q1 = wr[1], q2 = wr[2], q3 = wr[3];            \
        ull w8 = ((const ull*)wr)[8];                                         \
        acc[ol][0] = fma2(P[0][0], q0.x, acc[ol][0]);                         \
        acc[ol][0] = fma2(P[0][1], q0.y, acc[ol][0]);                         \
        acc[ol][0] = fma2(P[0][2], q1.x, acc[ol][0]);                         \
        acc[ol][0] = fma2(P[1][0], q1.y, acc[ol][0]);                         \
        acc[ol][0] = fma2(P[1][1], q2.x, acc[ol][0]);                         \
        acc[ol][0] = fma2(P[1][2], q2.y, acc[ol][0]);                         \
        acc[ol][0] = fma2(P[2][0], q3.x, acc[ol][0]);                         \
        acc[ol][0] = fma2(P[2][1], q3.y, acc[ol][0]);                         \
        acc[ol][0] = fma2(P[2][2], w8,   acc[ol][0]);                         \
        acc[ol][1] = fma2(P[0][2], q0.x, acc[ol][1]);                         \
        acc[ol][1] = fma2(P[0][3], q0.y, acc[ol][1]);                         \
        acc[ol][1] = fma2(P[0][4], q1.x, acc[ol][1]);                         \
        acc[ol][1] = fma2(P[1][2], q1.y, acc[ol][1]);                         \
        acc[ol][1] = fma2(P[1][3], q2.x, acc[ol][1]);                         \
        acc[ol][1] = fma2(P[1][4], q2.y, acc[ol][1]);                         \
        acc[ol][1] = fma2(P[2][2], q3.x, acc[ol][1]);                         \
        acc[ol][1] = fma2(P[2][3], q3.y, acc[ol][1]);                         \
        acc[ol][1] = fma2(P[2][4], w8,   acc[ol][1]);                         \
    } while (0)

__global__ __launch_bounds__(256, 2)
void conv_kernel(const float* __restrict__ x,
                 const float* __restrict__ bias,
                 float* __restrict__ out) {
    __shared__ __align__(16) float patch[18 * 66];
    __shared__ int   S[513];
    __shared__ __align__(16) ull ws[WCAP * 10];

    int bz = blockIdx.z;
    int b = bz >> 3, og = bz & 7;
    int h0 = blockIdx.y * 16, w0 = blockIdx.x * 64;
    int t = threadIdx.x, ty = t >> 4, tx = t & 15;

    // Stage CSR slice for this group: bins [og*512, og*512+512].
    for (int e = t; e < 513; e += 256) S[e] = g_start[(og << 9) + e];

    // Accumulators initialized with bias (both halves of each pair).
    ull acc[OG][2];
#pragma unroll
    for (int ol = 0; ol < OG; ol++) {
        float bv = bias[og * OG + ol];
        acc[ol][0] = pk2(bv, bv);
        acc[ol][1] = acc[ol][0];
    }
    __syncthreads();

    // Stage this group's weight entries (contiguous slots [S[0], S[512])).
    // conn_out = repeat(arange(64),16) -> each group has exactly 128 entries,
    // so nE==128 <= WCAP and the overflow path below is dead (kept for safety).
    int jb = S[0];
    int nE = S[512] - jb;
    int nStage = nE < WCAP ? nE : WCAP;
    for (int e = t; e < nStage * 10; e += 256) ws[e] = g_w[(size_t)jb * 10 + e];
    int jcap = jb + nStage;

    const float* xb = x + (size_t)b * NIN * HH * WW;

    for (int i = 0; i < NIN; i++) {
        int s0 = S[i * 8], s1 = S[i * 8 + 8];
        if (s0 == s1) continue;  // uniform across block: no channel users -> skip

        __syncthreads();  // prior consumers done (also orders ws stage on 1st pass)
        const float* xc = xb + i * HH * WW;
        for (int e = t; e < 18 * 66; e += 256) {
            int r = e / 66, c = e - r * 66;
            int ih = h0 + r; if (ih > HH - 1) ih = HH - 1;
            int iw = w0 + c; if (iw > WW - 1) iw = WW - 1;
            patch[e] = xc[ih * WW + iw];
        }
        __syncthreads();

        // Build shifted input pairs for this thread's 4 pixels x 3 tap rows.
        ull P[3][5];
#pragma unroll
        for (int r = 0; r < 3; r++) {
            const float2* row = (const float2*)&patch[(ty + r) * 66 + tx * 4];
            float2 a = row[0], bq = row[1], cq = row[2];
            P[r][0] = pk2(a.x, a.y);
            P[r][1] = pk2(a.y, bq.x);
            P[r][2] = pk2(bq.x, bq.y);
            P[r][3] = pk2(bq.y, cq.x);
            P[r][4] = pk2(cq.x, cq.y);
        }

        int j = s0;
#pragma unroll
        for (int ol = 0; ol < OG; ol++) {
            int e1 = S[i * 8 + ol + 1];
            int e1s = e1 < jcap ? e1 : jcap;
            for (; j < e1s; ++j) CONV_INNER(&ws[(size_t)(j - jb) * 10]);   // smem path
            for (; j < e1;  ++j) CONV_INNER(&g_w[(size_t)j * 10]);        // overflow path
        }
    }

    // Store (8B-aligned float2 stores; WO=190 so full float4 alignment is not
    // guaranteed). rem is always 2 or >=4.
    int h = h0 + ty;
    if (h < HO) {
        int wb = w0 + tx * 4;
        int rem = WO - wb;
        float* ob = out + (((size_t)(b * NOUT + og * OG)) * HO + h) * WO + wb;
#pragma unroll
        for (int ol = 0; ol < OG; ol++) {
            float2 lo, hi;
            asm("mov.b64 {%0, %1}, %2;" : "=f"(lo.x), "=f"(lo.y) : "l"(acc[ol][0]));
            asm("mov.b64 {%0, %1}, %2;" : "=f"(hi.x), "=f"(hi.y) : "l"(acc[ol][1]));
            float* p = ob + (size_t)ol * HO * WO;
            *(float2*)p = lo;
            if (rem >= 4) *(float2*)(p + 2) = hi;
        }
    }
}

// ---------------------------------------------------------------------------
// Launch: prep (rebuilds tables deterministically every call) then main conv.
// Both graph-capturable: plain launches, no sync, no allocation.
// ---------------------------------------------------------------------------
extern "C" void kernel_launch(void* const* d_in, const int* in_sizes, int n_in,
                              void* d_out, int out_size) {
    const float* x    = (const float*)d_in[0];
    const float* w    = (const float*)d_in[1];
    const float* bias = (const float*)d_in[2];
    const int*   cin  = (const int*)d_in[3];
    const int*   cout = (const int*)d_in[4];
    int K = in_sizes[3];                       // 1024
    int B = in_sizes[0] / (NIN * HH * WW);     // 4

    prep_kernel<<<1, 1024>>>(w, cin, cout, K);

    dim3 grid((WO + 63) / 64, (HO + 15) / 16, B * NG);
    conv_kernel<<<grid, 256>>>(x, bias, (float*)d_out);
}

// round 4
// speedup vs baseline: 1.8684x; 1.8684x over previous
#include <cuda_runtime.h>
#include <cstdint>

// Problem constants.
#define NIN   64
#define NOUT  64
#define HH    192
#define WW    192
#define HO    190
#define WO    190
#define OG    8            // output channels per block
#define NG    (NOUT / OG)  // 8 groups
#define MAXK  2048
#define WCAP  256          // smem-staged weight entries per block (actual = 128)
#define PST   68           // patch row stride in floats (272B, 16B-aligned rows)
#define PROWS 18
#define PBUF  (PROWS * PST)

typedef unsigned long long ull;

__device__ int g_start[NG * 512 + 1];
__device__ __align__(16) ull g_w[MAXK * 10];

__device__ __forceinline__ ull pk2(float lo, float hi) {
    ull r;
    asm("mov.b64 %0, {%1, %2};" : "=l"(r) : "f"(lo), "f"(hi));
    return r;
}
__device__ __forceinline__ ull fma2(ull a, ull b, ull c) {
    ull d;
    asm("fma.rn.f32x2 %0, %1, %2, %3;" : "=l"(d) : "l"(a), "l"(b), "l"(c));
    return d;
}
__device__ __forceinline__ void cpa16(uint32_t d, const void* s) {
    asm volatile("cp.async.ca.shared.global [%0], [%1], 16;" :: "r"(d), "l"(s));
}
__device__ __forceinline__ void cpa8(uint32_t d, const void* s) {
    asm volatile("cp.async.ca.shared.global [%0], [%1], 8;" :: "r"(d), "l"(s));
}
__device__ __forceinline__ void cpcommit() { asm volatile("cp.async.commit_group;"); }
__device__ __forceinline__ void cpwait0()  { asm volatile("cp.async.wait_group 0;"); }

// ---------------------------------------------------------------------------
// Prep (known-correct): CSR over (og, in_ch, ol) bins plus duplicated (w,w)
// f32x2 weight pairs.
// ---------------------------------------------------------------------------
__global__ void prep_kernel(const float* __restrict__ w,
                            const int* __restrict__ cin,
                            const int* __restrict__ cout,
                            int K) {
    __shared__ int cnt[4096];
    __shared__ int part[1024];
    int t = threadIdx.x;

    for (int e = t; e < 4096; e += 1024) cnt[e] = 0;
    __syncthreads();

    for (int k = t; k < K; k += 1024) {
        int o = cout[k], i = cin[k];
        int bin = ((o >> 3) << 9) | (i << 3) | (o & 7);
        atomicAdd(&cnt[bin], 1);
    }
    __syncthreads();

    int c4[4];
    int s = 0;
#pragma unroll
    for (int q = 0; q < 4; q++) { c4[q] = cnt[t * 4 + q]; s += c4[q]; }
    part[t] = s;
    __syncthreads();
    for (int off = 1; off < 1024; off <<= 1) {
        int v = (t >= off) ? part[t - off] : 0;
        __syncthreads();
        part[t] += v;
        __syncthreads();
    }
    int run = part[t] - s;
#pragma unroll
    for (int q = 0; q < 4; q++) {
        int bin = t * 4 + q;
        int c = c4[q];
        cnt[bin] = run;
        g_start[bin] = run;
        run += c;
    }
    if (t == 1023) g_start[4096] = run;
    __syncthreads();

    for (int k = t; k < K; k += 1024) {
        int o = cout[k], i = cin[k];
        int bin = ((o >> 3) << 9) | (i << 3) | (o & 7);
        int slot = atomicAdd(&cnt[bin], 1);
        if (slot < MAXK) {
            ull* dst = &g_w[(size_t)slot * 10];
#pragma unroll
            for (int q = 0; q < 9; q++) {
                float wv = w[k * 9 + q];
                dst[q] = pk2(wv, wv);
            }
            dst[9] = 0;
        }
    }
}

// ---------------------------------------------------------------------------
// Inner body: 18 FMA2 per entry, acc0/acc1 chains interleaved for latency.
// ---------------------------------------------------------------------------
#define CONV_INNER(WRPTR)                                                     \
    do {                                                                      \
        const ulonglong2* wr = (const ulonglong2*)(WRPTR);                    \
        ulonglong2 q0 = wr[0], q1 = wr[1], q2 = wr[2], q3 = wr[3];            \
        ull w8 = ((const ull*)wr)[8];                                         \
        acc[ol][0] = fma2(P[0][0], q0.x, acc[ol][0]);                         \
        acc[ol][1] = fma2(P[0][2], q0.x, acc[ol][1]);                         \
        acc[ol][0] = fma2(P[0][1], q0.y, acc[ol][0]);                         \
        acc[ol][1] = fma2(P[0][3], q0.y, acc[ol][1]);                         \
        acc[ol][0] = fma2(P[0][2], q1.x, acc[ol][0]);                         \
        acc[ol][1] = fma2(P[0][4], q1.x, acc[ol][1]);                         \
        acc[ol][0] = fma2(P[1][0], q1.y, acc[ol][0]);                         \
        acc[ol][1] = fma2(P[1][2], q1.y, acc[ol][1]);                         \
        acc[ol][0] = fma2(P[1][1], q2.x, acc[ol][0]);                         \
        acc[ol][1] = fma2(P[1][3], q2.x, acc[ol][1]);                         \
        acc[ol][0] = fma2(P[1][2], q2.y, acc[ol][0]);                         \
        acc[ol][1] = fma2(P[1][4], q2.y, acc[ol][1]);                         \
        acc[ol][0] = fma2(P[2][0], q3.x, acc[ol][0]);                         \
        acc[ol][1] = fma2(P[2][2], q3.x, acc[ol][1]);                         \
        acc[ol][0] = fma2(P[2][1], q3.y, acc[ol][0]);                         \
        acc[ol][1] = fma2(P[2][3], q3.y, acc[ol][1]);                         \
        acc[ol][0] = fma2(P[2][2], w8,   acc[ol][0]);                         \
        acc[ol][1] = fma2(P[2][4], w8,   acc[ol][1]);                         \
    } while (0)

__global__ __launch_bounds__(256, 3)
void conv_kernel(const float* __restrict__ x,
                 const float* __restrict__ bias,
                 float* __restrict__ out) {
    __shared__ __align__(16) float patch[2][PBUF];
    __shared__ int S[513];
    __shared__ __align__(16) ull ws[WCAP * 10];
    __shared__ unsigned umask[2];

    int bz = blockIdx.z;
    int b = bz >> 3, og = bz & 7;
    int h0 = blockIdx.y * 16, w0 = blockIdx.x * 64;
    int t = threadIdx.x, ty = t >> 4, tx = t & 15;

    for (int e = t; e < 513; e += 256) S[e] = g_start[(og << 9) + e];
    __syncthreads();

    // Used-channel bitmask via warp ballots (threads 0..63 = warps 0,1 whole).
    if (t < 64) {
        int used = S[t * 8] != S[t * 8 + 8];
        unsigned m = __ballot_sync(0xFFFFFFFFu, used);
        if ((t & 31) == 0) umask[t >> 5] = m;
    }

    // Stage weights for this group.
    int jb = S[0];
    int nE = S[512] - jb;
    int nStage = nE < WCAP ? nE : WCAP;
    for (int e = t; e < nStage * 10; e += 256) ws[e] = g_w[(size_t)jb * 10 + e];
    int jcap = jb + nStage;

    ull acc[OG][2];
#pragma unroll
    for (int ol = 0; ol < OG; ol++) {
        float bv = bias[og * OG + ol];
        acc[ol][0] = pk2(bv, bv);
        acc[ol][1] = acc[ol][0];
    }
    __syncthreads();

    unsigned m0 = umask[0], m1 = umask[1];
    uint32_t pbase = (uint32_t)__cvta_generic_to_shared(&patch[0][0]);
    const float* xb = x + (size_t)b * NIN * HH * WW;
    bool tailok = (w0 <= WW - 68);  // w0 in {0,64}: patch cols 64,65 valid

    // --- pipelined channel loop: prefetch next patch via cp.async while
    //     computing the current one; one barrier per channel. ---
#define POPNEXT(dst)                                                          \
    do {                                                                      \
        if (m0)      { dst = __ffs(m0) - 1;      m0 &= m0 - 1; }              \
        else if (m1) { dst = __ffs(m1) + 31;     m1 &= m1 - 1; }              \
        else dst = -1;                                                        \
    } while (0)

#define PREFETCH(ch, buf)                                                     \
    do {                                                                      \
        const float* xc = xb + (ch) * (HH * WW);                              \
        uint32_t sb = pbase + (buf) * (PBUF * 4);                             \
        _Pragma("unroll")                                                     \
        for (int rr = ty; rr < PROWS; rr += 16) {                             \
            int ih = h0 + rr; if (ih > HH - 1) ih = HH - 1;                   \
            const float* rg = xc + ih * WW + w0;                              \
            cpa16(sb + (rr * PST + tx * 4) * 4, rg + tx * 4);                 \
            if (tx == 0 && tailok) cpa8(sb + (rr * PST + 64) * 4, rg + 64);   \
        }                                                                     \
    } while (0)

    int i;
    POPNEXT(i);
    if (i >= 0) PREFETCH(i, 0);
    cpcommit();
    int cur = 0;

    while (i >= 0) {
        int nx;
        POPNEXT(nx);
        cpwait0();
        __syncthreads();
        if (nx >= 0) PREFETCH(nx, cur ^ 1);
        cpcommit();

        // Build shifted input pairs for this thread's 4 px x 3 tap rows.
        const float* pb = &patch[cur][ty * PST + tx * 4];
        ull P[3][5];
#pragma unroll
        for (int r = 0; r < 3; r++) {
            float2 a  = *(const float2*)(pb + r * PST);
            float2 bq = *(const float2*)(pb + r * PST + 2);
            float2 cq = *(const float2*)(pb + r * PST + 4);
            P[r][0] = pk2(a.x, a.y);
            P[r][1] = pk2(a.y, bq.x);
            P[r][2] = pk2(bq.x, bq.y);
            P[r][3] = pk2(bq.y, cq.x);
            P[r][4] = pk2(cq.x, cq.y);
        }

        int j = S[i * 8];
        const ull* wp = &ws[(size_t)(j - jb) * 10];
#pragma unroll
        for (int ol = 0; ol < OG; ol++) {
            int e1 = S[i * 8 + ol + 1];
            int e1s = e1 < jcap ? e1 : jcap;
            for (; j < e1s; ++j, wp += 10) CONV_INNER(wp);       // smem path
            for (; j < e1;  ++j) CONV_INNER(&g_w[(size_t)j * 10]); // overflow
        }

        cur ^= 1;
        i = nx;
    }

    // Store: 8B-aligned float2 stores; rem is 2 or >=4 for all tiles.
    int h = h0 + ty;
    if (h < HO) {
        int wb = w0 + tx * 4;
        int rem = WO - wb;
        float* ob = out + (((size_t)(b * NOUT + og * OG)) * HO + h) * WO + wb;
#pragma unroll
        for (int ol = 0; ol < OG; ol++) {
            float2 lo, hi;
            asm("mov.b64 {%0, %1}, %2;" : "=f"(lo.x), "=f"(lo.y) : "l"(acc[ol][0]));
            asm("mov.b64 {%0, %1}, %2;" : "=f"(hi.x), "=f"(hi.y) : "l"(acc[ol][1]));
            float* p = ob + (size_t)ol * HO * WO;
            *(float2*)p = lo;
            if (rem >= 4) *(float2*)(p + 2) = hi;
        }
    }
}

// ---------------------------------------------------------------------------
extern "C" void kernel_launch(void* const* d_in, const int* in_sizes, int n_in,
                              void* d_out, int out_size) {
    const float* x    = (const float*)d_in[0];
    const float* w    = (const float*)d_in[1];
    const float* bias = (const float*)d_in[2];
    const int*   cin  = (const int*)d_in[3];
    const int*   cout = (const int*)d_in[4];
    int K = in_sizes[3];                       // 1024
    int B = in_sizes[0] / (NIN * HH * WW);     // 4

    prep_kernel<<<1, 1024>>>(w, cin, cout, K);

    dim3 grid((WO + 63) / 64, (HO + 15) / 16, B * NG);
    conv_kernel<<<grid, 256>>>(x, bias, (float*)d_out);
}

// round 5
// speedup vs baseline: 2.2652x; 1.2124x over previous
#include <cuda_runtime.h>
#include <cstdint>

// Problem constants.
#define NIN   64
#define NOUT  64
#define HH    192
#define WW    192
#define HO    190
#define WO    190
#define OG    8            // output channels per block
#define NG    (NOUT / OG)  // 8 groups
#define MAXK  2048
#define WCAP  256          // smem-staged weight entries per block (actual = 128)
#define TROWS 24           // output rows per block
#define PROWS 26           // patch rows (TROWS + 2 halo)
#define PST   68           // patch row stride in floats (272B, 16B-aligned rows)
#define PBUF  (PROWS * PST)
#define TH    384

typedef unsigned long long ull;

__device__ int g_start[NG * 512 + 1];
__device__ ull g_cnt[NG * 64];            // per (og, in_ch): 8x8-bit ol counts
__device__ __align__(16) ull g_w[MAXK * 10];

__device__ __forceinline__ ull pk2(float lo, float hi) {
    ull r;
    asm("mov.b64 %0, {%1, %2};" : "=l"(r) : "f"(lo), "f"(hi));
    return r;
}
__device__ __forceinline__ ull fma2(ull a, ull b, ull c) {
    ull d;
    asm("fma.rn.f32x2 %0, %1, %2, %3;" : "=l"(d) : "l"(a), "l"(b), "l"(c));
    return d;
}
__device__ __forceinline__ void cpa16(uint32_t d, const void* s) {
    asm volatile("cp.async.ca.shared.global [%0], [%1], 16;" :: "r"(d), "l"(s));
}
__device__ __forceinline__ void cpa8(uint32_t d, const void* s) {
    asm volatile("cp.async.ca.shared.global [%0], [%1], 8;" :: "r"(d), "l"(s));
}
__device__ __forceinline__ void cpcommit() { asm volatile("cp.async.commit_group;"); }
__device__ __forceinline__ void cpwait0()  { asm volatile("cp.async.wait_group 0;"); }

// ---------------------------------------------------------------------------
// Prep: CSR over (og, in_ch, ol) bins, duplicated (w,w) f32x2 weight pairs,
// plus packed per-(og,in_ch) ol-count u64s.
// ---------------------------------------------------------------------------
__global__ void prep_kernel(const float* __restrict__ w,
                            const int* __restrict__ cin,
                            const int* __restrict__ cout,
                            int K) {
    __shared__ int cnt[4096];
    __shared__ int part[1024];
    int t = threadIdx.x;

    for (int e = t; e < 4096; e += 1024) cnt[e] = 0;
    __syncthreads();

    for (int k = t; k < K; k += 1024) {
        int o = cout[k], i = cin[k];
        int bin = ((o >> 3) << 9) | (i << 3) | (o & 7);
        atomicAdd(&cnt[bin], 1);
    }
    __syncthreads();

    int c4[4];
    int s = 0;
#pragma unroll
    for (int q = 0; q < 4; q++) { c4[q] = cnt[t * 4 + q]; s += c4[q]; }
    part[t] = s;
    __syncthreads();
    for (int off = 1; off < 1024; off <<= 1) {
        int v = (t >= off) ? part[t - off] : 0;
        __syncthreads();
        part[t] += v;
        __syncthreads();
    }
    int run = part[t] - s;
#pragma unroll
    for (int q = 0; q < 4; q++) {
        int bin = t * 4 + q;
        int c = c4[q];
        cnt[bin] = run;
        g_start[bin] = run;
        run += c;
    }
    if (t == 1023) g_start[4096] = run;
    __syncthreads();

    // Packed counts: one u64 per (og, in_ch) = 8 bytes of ol-counts.
    // (counts from the smem cursor array before scatter mutates it: use c4?
    //  simplest correct source: recompute from g_start via smem 'part' sync —
    //  but cnt[] currently holds start offsets (pre-scatter). diff of starts
    //  of adjacent bins == count only within this thread's 4 bins; use gmem
    //  g_start instead, which is complete.)
    __syncthreads();
    for (int e = t; e < NG * 64; e += 1024) {
        ull v = 0;
#pragma unroll
        for (int q = 0; q < 8; q++) {
            int c = g_start[e * 8 + q + 1] - g_start[e * 8 + q];
            v |= (ull)(unsigned)(c & 255) << (8 * q);
        }
        g_cnt[e] = v;
    }

    for (int k = t; k < K; k += 1024) {
        int o = cout[k], i = cin[k];
        int bin = ((o >> 3) << 9) | (i << 3) | (o & 7);
        int slot = atomicAdd(&cnt[bin], 1);
        if (slot < MAXK) {
            ull* dst = &g_w[(size_t)slot * 10];
#pragma unroll
            for (int q = 0; q < 9; q++) {
                float wv = w[k * 9 + q];
                dst[q] = pk2(wv, wv);
            }
            dst[9] = 0;
        }
    }
}

// ---------------------------------------------------------------------------
// Inner body: 18 FMA2 per entry, acc0/acc1 chains interleaved.
// ---------------------------------------------------------------------------
#define CONV_INNER(WRPTR)                                                     \
    do {                                                                      \
        const ulonglong2* wr = (const ulonglong2*)(WRPTR);                    \
        ulonglong2 q0 = wr[0], q1 = wr[1], q2 = wr[2], q3 = wr[3];            \
        ull w8 = ((const ull*)wr)[8];                                         \
        acc[ol][0] = fma2(P[0][0], q0.x, acc[ol][0]);                         \
        acc[ol][1] = fma2(P[0][2], q0.x, acc[ol][1]);                         \
        acc[ol][0] = fma2(P[0][1], q0.y, acc[ol][0]);                         \
        acc[ol][1] = fma2(P[0][3], q0.y, acc[ol][1]);                         \
        acc[ol][0] = fma2(P[0][2], q1.x, acc[ol][0]);                         \
        acc[ol][1] = fma2(P[0][4], q1.x, acc[ol][1]);                         \
        acc[ol][0] = fma2(P[1][0], q1.y, acc[ol][0]);                         \
        acc[ol][1] = fma2(P[1][2], q1.y, acc[ol][1]);                         \
        acc[ol][0] = fma2(P[1][1], q2.x, acc[ol][0]);                         \
        acc[ol][1] = fma2(P[1][3], q2.x, acc[ol][1]);                         \
        acc[ol][0] = fma2(P[1][2], q2.y, acc[ol][0]);                         \
        acc[ol][1] = fma2(P[1][4], q2.y, acc[ol][1]);                         \
        acc[ol][0] = fma2(P[2][0], q3.x, acc[ol][0]);                         \
        acc[ol][1] = fma2(P[2][2], q3.x, acc[ol][1]);                         \
        acc[ol][0] = fma2(P[2][1], q3.y, acc[ol][0]);                         \
        acc[ol][1] = fma2(P[2][3], q3.y, acc[ol][1]);                         \
        acc[ol][0] = fma2(P[2][2], w8,   acc[ol][0]);                         \
        acc[ol][1] = fma2(P[2][4], w8,   acc[ol][1]);                         \
    } while (0)

#define PREFETCH(ch, buf)                                                     \
    do {                                                                      \
        const float* xc = xb + (ch) * (HH * WW);                              \
        uint32_t sb = pbase + (buf) * (PBUF * 4);                             \
        cpa16(sb + sd0, xc + go0);                                            \
        if (has1) cpa16(sb + sd1, xc + go1);                                  \
        if (tail) cpa8(sb + sdt, xc + got);                                   \
    } while (0)

// Channel loop over either smem-staged weights (hot) or gmem (overflow-safe).
#define RUN_CHANNELS(WBASE)                                                   \
    do {                                                                      \
        const ull* wp = (WBASE);                                              \
        ull m = mask;                                                         \
        int i = m ? (__ffsll((long long)m) - 1) : -1;                         \
        m &= m - 1;                                                           \
        if (i >= 0) PREFETCH(i, 0);                                           \
        cpcommit();                                                           \
        int cur = 0;                                                          \
        while (i >= 0) {                                                      \
            int nx = m ? (__ffsll((long long)m) - 1) : -1;                    \
            m &= m - 1;                                                       \
            cpwait0();                                                        \
            __syncthreads();                                                  \
            if (nx >= 0) PREFETCH(nx, cur ^ 1);                               \
            cpcommit();                                                       \
            const float* pb = &patch[cur][ty * PST + tx * 4];                 \
            ull P[3][5];                                                      \
            _Pragma("unroll")                                                 \
            for (int r = 0; r < 3; r++) {                                     \
                float4 a4 = *(const float4*)(pb + r * PST);                   \
                float2 c2 = *(const float2*)(pb + r * PST + 4);               \
                P[r][0] = pk2(a4.x, a4.y);                                    \
                P[r][1] = pk2(a4.y, a4.z);                                    \
                P[r][2] = pk2(a4.z, a4.w);                                    \
                P[r][3] = pk2(a4.w, c2.x);                                    \
                P[r][4] = pk2(c2.x, c2.y);                                    \
            }                                                                 \
            ull cnts = cw[i];                                                 \
            _Pragma("unroll")                                                 \
            for (int ol = 0; ol < OG; ol++) {                                 \
                int n = (int)((cnts >> (8 * ol)) & 255);                      \
                while (n--) { CONV_INNER(wp); wp += 10; }                     \
            }                                                                 \
            cur ^= 1;                                                         \
            i = nx;                                                           \
        }                                                                     \
    } while (0)

__global__ __launch_bounds__(TH, 2)
void conv_kernel(const float* __restrict__ x,
                 const float* __restrict__ bias,
                 float* __restrict__ out) {
    __shared__ __align__(16) float patch[2][PBUF];
    __shared__ __align__(16) ull ws[WCAP * 10];
    __shared__ ull cw[64];
    __shared__ unsigned umask[2];

    int bz = blockIdx.z;
    int b = bz >> 3, og = bz & 7;
    int h0 = blockIdx.y * TROWS, w0 = blockIdx.x * 64;
    int t = threadIdx.x, ty = t >> 4, tx = t & 15;

    // Stage packed counts; build used-channel ballot (warps 0,1 whole).
    if (t < 64) {
        ull c = g_cnt[(og << 6) + t];
        cw[t] = c;
        unsigned mm = __ballot_sync(0xFFFFFFFFu, c != 0);
        if ((t & 31) == 0) umask[t >> 5] = mm;
    }

    int jb = g_start[og << 9];
    int nE = g_start[(og << 9) + 512] - jb;
    int nStage = nE < WCAP ? nE : WCAP;
    for (int e = t; e < nStage * 10; e += TH) ws[e] = g_w[(size_t)jb * 10 + e];

    ull acc[OG][2];
#pragma unroll
    for (int ol = 0; ol < OG; ol++) {
        float bv = bias[og * OG + ol];
        acc[ol][0] = pk2(bv, bv);
        acc[ol][1] = acc[ol][0];
    }
    __syncthreads();

    ull mask = (ull)umask[0] | ((ull)umask[1] << 32);
    uint32_t pbase = (uint32_t)__cvta_generic_to_shared(&patch[0][0]);
    const float* xb = x + (size_t)b * NIN * HH * WW;

    // Hoisted loader addressing: 26 rows x 16 cols of 16B -> 416 slots over
    // 384 threads (threads t<32 take a second slot); + one 8B tail per row.
    int r0 = t >> 4, c0 = (t & 15) * 4;
    int ih0 = h0 + r0; if (ih0 > HH - 1) ih0 = HH - 1;
    int go0 = ih0 * WW + w0 + c0;
    uint32_t sd0 = (uint32_t)(r0 * PST + c0) * 4;
    bool has1 = t < (PROWS * 16 - TH);          // t < 32
    int r1 = (t + TH) >> 4, c1 = ((t + TH) & 15) * 4;
    int ih1 = h0 + r1; if (ih1 > HH - 1) ih1 = HH - 1;
    int go1 = ih1 * WW + w0 + c1;
    uint32_t sd1 = (uint32_t)(r1 * PST + c1) * 4;
    bool tail = (w0 <= WW - 68) && (t < PROWS);
    int iht = h0 + t; if (iht > HH - 1) iht = HH - 1;
    int got = iht * WW + w0 + 64;
    uint32_t sdt = (uint32_t)(t * PST + 64) * 4;

    if (nE <= WCAP) {
        RUN_CHANNELS(ws);
    } else {
        RUN_CHANNELS(&g_w[(size_t)jb * 10]);    // safety fallback (not hit)
    }

    // Store: 8B-aligned float2 stores; rem is 2 or >=4 for all tiles.
    int h = h0 + ty;
    if (h < HO) {
        int wb = w0 + tx * 4;
        int rem = WO - wb;
        float* ob = out + (((size_t)(b * NOUT + og * OG)) * HO + h) * WO + wb;
#pragma unroll
        for (int ol = 0; ol < OG; ol++) {
            float2 lo, hi;
            asm("mov.b64 {%0, %1}, %2;" : "=f"(lo.x), "=f"(lo.y) : "l"(acc[ol][0]));
            asm("mov.b64 {%0, %1}, %2;" : "=f"(hi.x), "=f"(hi.y) : "l"(acc[ol][1]));
            float* p = ob + (size_t)ol * HO * WO;
            *(float2*)p = lo;
            if (rem >= 4) *(float2*)(p + 2) = hi;
        }
    }
}

// ---------------------------------------------------------------------------
extern "C" void kernel_launch(void* const* d_in, const int* in_sizes, int n_in,
                              void* d_out, int out_size) {
    const float* x    = (const float*)d_in[0];
    const float* w    = (const float*)d_in[1];
    const float* bias = (const float*)d_in[2];
    const int*   cin  = (const int*)d_in[3];
    const int*   cout = (const int*)d_in[4];
    int K = in_sizes[3];                       // 1024
    int B = in_sizes[0] / (NIN * HH * WW);     // 4

    prep_kernel<<<1, 1024>>>(w, cin, cout, K);

    dim3 grid((WO + 63) / 64, (HO + TROWS - 1) / TROWS, B * NG);
    conv_kernel<<<grid, TH>>>(x, bias, (float*)d_out);
}

// round 6
// speedup vs baseline: 2.4813x; 1.0954x over previous
#include <cuda_runtime.h>
#include <cstdint>

// Problem constants.
#define NIN   64
#define NOUT  64
#define HH    192
#define WW    192
#define HO    190
#define WO    190
#define OG    8            // output channels per block
#define NG    (NOUT / OG)  // 8 groups
#define MAXK  2048
#define WCAP  256          // smem-staged weight entries per block (actual = 128)
#define TROWS 16           // output rows per block
#define TCOLS 96           // output cols per block (6 px per thread x 16 tx)
#define PROWS 18           // patch rows
#define PST   100          // patch row stride in floats (400B, 16B-aligned rows)
#define PBUF  (PROWS * PST)
#define TH    256

typedef unsigned long long ull;

__device__ int g_start[NG * 512 + 1];
__device__ ull g_cnt[NG * 64];            // per (og, in_ch): 8x8-bit ol counts
__device__ __align__(16) ull g_w[MAXK * 10];

__device__ __forceinline__ ull pk2(float lo, float hi) {
    ull r;
    asm("mov.b64 %0, {%1, %2};" : "=l"(r) : "f"(lo), "f"(hi));
    return r;
}
__device__ __forceinline__ ull fma2(ull a, ull b, ull c) {
    ull d;
    asm("fma.rn.f32x2 %0, %1, %2, %3;" : "=l"(d) : "l"(a), "l"(b), "l"(c));
    return d;
}
__device__ __forceinline__ void cpa16(uint32_t d, const void* s) {
    asm volatile("cp.async.ca.shared.global [%0], [%1], 16;" :: "r"(d), "l"(s));
}
__device__ __forceinline__ void cpcommit() { asm volatile("cp.async.commit_group;"); }
__device__ __forceinline__ void cpwait0()  { asm volatile("cp.async.wait_group 0;"); }

// ---------------------------------------------------------------------------
// Prep (known-correct): CSR over (og, in_ch, ol) bins, duplicated (w,w) f32x2
// weight pairs, plus packed per-(og,in_ch) ol-count u64s.
// ---------------------------------------------------------------------------
__global__ void prep_kernel(const float* __restrict__ w,
                            const int* __restrict__ cin,
                            const int* __restrict__ cout,
                            int K) {
    __shared__ int cnt[4096];
    __shared__ int part[1024];
    int t = threadIdx.x;

    for (int e = t; e < 4096; e += 1024) cnt[e] = 0;
    __syncthreads();

    for (int k = t; k < K; k += 1024) {
        int o = cout[k], i = cin[k];
        int bin = ((o >> 3) << 9) | (i << 3) | (o & 7);
        atomicAdd(&cnt[bin], 1);
    }
    __syncthreads();

    int c4[4];
    int s = 0;
#pragma unroll
    for (int q = 0; q < 4; q++) { c4[q] = cnt[t * 4 + q]; s += c4[q]; }
    part[t] = s;
    __syncthreads();
    for (int off = 1; off < 1024; off <<= 1) {
        int v = (t >= off) ? part[t - off] : 0;
        __syncthreads();
        part[t] += v;
        __syncthreads();
    }
    int run = part[t] - s;
#pragma unroll
    for (int q = 0; q < 4; q++) {
        int bin = t * 4 + q;
        int c = c4[q];
        cnt[bin] = run;
        g_start[bin] = run;
        run += c;
    }
    if (t == 1023) g_start[4096] = run;
    __syncthreads();

    // Packed per-(og,in_ch) ol counts from the completed CSR.
    for (int e = t; e < NG * 64; e += 1024) {
        ull v = 0;
#pragma unroll
        for (int q = 0; q < 8; q++) {
            int c = g_start[e * 8 + q + 1] - g_start[e * 8 + q];
            v |= (ull)(unsigned)(c & 255) << (8 * q);
        }
        g_cnt[e] = v;
    }

    for (int k = t; k < K; k += 1024) {
        int o = cout[k], i = cin[k];
        int bin = ((o >> 3) << 9) | (i << 3) | (o & 7);
        int slot = atomicAdd(&cnt[bin], 1);
        if (slot < MAXK) {
            ull* dst = &g_w[(size_t)slot * 10];
#pragma unroll
            for (int q = 0; q < 9; q++) {
                float wv = w[k * 9 + q];
                dst[q] = pk2(wv, wv);
            }
            dst[9] = 0;
        }
    }
}

// ---------------------------------------------------------------------------
// Inner body: 27 FMA2 per entry (3 pixel-pairs), 3 chains interleaved.
// Weight order: q0=(w00,w01) q1=(w02,w10) q2=(w11,w12) q3=(w20,w21) w8=w22.
// Pair p uses P[r][2p], P[r][2p+1], P[r][2p+2].
// ---------------------------------------------------------------------------
#define CONV_INNER(WRPTR)                                                     \
    do {                                                                      \
        const ulonglong2* wr = (const ulonglong2*)(WRPTR);                    \
        ulonglong2 q0 = wr[0], q1 = wr[1], q2 = wr[2], q3 = wr[3];            \
        ull w8 = ((const ull*)wr)[8];                                         \
        acc[ol][0] = fma2(P[0][0], q0.x, acc[ol][0]);                         \
        acc[ol][1] = fma2(P[0][2], q0.x, acc[ol][1]);                         \
        acc[ol][2] = fma2(P[0][4], q0.x, acc[ol][2]);                         \
        acc[ol][0] = fma2(P[0][1], q0.y, acc[ol][0]);                         \
        acc[ol][1] = fma2(P[0][3], q0.y, acc[ol][1]);                         \
        acc[ol][2] = fma2(P[0][5], q0.y, acc[ol][2]);                         \
        acc[ol][0] = fma2(P[0][2], q1.x, acc[ol][0]);                         \
        acc[ol][1] = fma2(P[0][4], q1.x, acc[ol][1]);                         \
        acc[ol][2] = fma2(P[0][6], q1.x, acc[ol][2]);                         \
        acc[ol][0] = fma2(P[1][0], q1.y, acc[ol][0]);                         \
        acc[ol][1] = fma2(P[1][2], q1.y, acc[ol][1]);                         \
        acc[ol][2] = fma2(P[1][4], q1.y, acc[ol][2]);                         \
        acc[ol][0] = fma2(P[1][1], q2.x, acc[ol][0]);                         \
        acc[ol][1] = fma2(P[1][3], q2.x, acc[ol][1]);                         \
        acc[ol][2] = fma2(P[1][5], q2.x, acc[ol][2]);                         \
        acc[ol][0] = fma2(P[1][2], q2.y, acc[ol][0]);                         \
        acc[ol][1] = fma2(P[1][4], q2.y, acc[ol][1]);                         \
        acc[ol][2] = fma2(P[1][6], q2.y, acc[ol][2]);                         \
        acc[ol][0] = fma2(P[2][0], q3.x, acc[ol][0]);                         \
        acc[ol][1] = fma2(P[2][2], q3.x, acc[ol][1]);                         \
        acc[ol][2] = fma2(P[2][4], q3.x, acc[ol][2]);                         \
        acc[ol][0] = fma2(P[2][1], q3.y, acc[ol][0]);                         \
        acc[ol][1] = fma2(P[2][3], q3.y, acc[ol][1]);                         \
        acc[ol][2] = fma2(P[2][5], q3.y, acc[ol][2]);                         \
        acc[ol][0] = fma2(P[2][2], w8,   acc[ol][0]);                         \
        acc[ol][1] = fma2(P[2][4], w8,   acc[ol][1]);                         \
        acc[ol][2] = fma2(P[2][6], w8,   acc[ol][2]);                         \
    } while (0)

#define PREFETCH(ch, buf)                                                     \
    do {                                                                      \
        const float* xc = xb + (ch) * (HH * WW);                              \
        uint32_t sb = pbase + (buf) * (PBUF * 4);                             \
        cpa16(sb + sd0, xc + go0);                                            \
        if (has1) cpa16(sb + sd1, xc + go1);                                  \
    } while (0)

__global__ __launch_bounds__(TH, 2)
void conv_kernel(const float* __restrict__ x,
                 const float* __restrict__ bias,
                 float* __restrict__ out) {
    __shared__ __align__(16) float patch[2][PBUF];
    __shared__ __align__(16) ull ws[WCAP * 10];
    __shared__ ull cw[64];
    __shared__ unsigned umask[2];

    int bz = blockIdx.z;
    int b = bz >> 3, og = bz & 7;
    int h0 = blockIdx.y * TROWS;
    int bx = blockIdx.x;
    int w0  = bx ? (WO - TCOLS) : 0;        // 0 or 94 (2-col overlap, benign)
    int w0a = w0 & ~3;                      // 16B-aligned patch origin (0 or 92)
    int xoff = w0 - w0a;                    // 0 or 2
    int t = threadIdx.x, ty = t >> 4, tx = t & 15;

    // Stage packed counts; build used-channel ballot (warps 0,1 whole).
    if (t < 64) {
        ull c = g_cnt[(og << 6) + t];
        cw[t] = c;
        unsigned mm = __ballot_sync(0xFFFFFFFFu, c != 0);
        if ((t & 31) == 0) umask[t >> 5] = mm;
    }

    int jb = g_start[og << 9];
    int nE = g_start[(og << 9) + 512] - jb;
    int nStage = nE < WCAP ? nE : WCAP;
    for (int e = t; e < nStage * 10; e += TH) ws[e] = g_w[(size_t)jb * 10 + e];

    ull acc[OG][3];
#pragma unroll
    for (int ol = 0; ol < OG; ol++) {
        float bv = bias[og * OG + ol];
        acc[ol][0] = pk2(bv, bv);
        acc[ol][1] = acc[ol][0];
        acc[ol][2] = acc[ol][0];
    }
    __syncthreads();

    ull mask = (ull)umask[0] | ((ull)umask[1] << 32);
    uint32_t pbase = (uint32_t)__cvta_generic_to_shared(&patch[0][0]);
    const float* xb = x + (size_t)b * NIN * HH * WW;

    // Hoisted loader addressing: 18 rows x 25 chunks of 16B = 450 slots over
    // 256 threads (threads t<194 take a second slot).
    int r0 = t / 25, c0 = (t - r0 * 25) * 4;
    int ih0 = h0 + r0; if (ih0 > HH - 1) ih0 = HH - 1;
    int go0 = ih0 * WW + w0a + c0;
    uint32_t sd0 = (uint32_t)(r0 * PST + c0) * 4;
    int s2 = t + TH;
    bool has1 = s2 < PROWS * 25;            // t < 194
    int r1 = s2 / 25, c1 = (s2 - r1 * 25) * 4;
    int ih1 = h0 + r1; if (ih1 > HH - 1) ih1 = HH - 1;
    int go1 = ih1 * WW + w0a + c1;
    uint32_t sd1 = (uint32_t)(r1 * PST + c1) * 4;

    // Pipelined channel loop: prefetch next patch while computing current.
    {
        const ull* wp = ws;
        ull m = mask;
        int i = m ? (__ffsll((long long)m) - 1) : -1;
        m &= m - 1;
        if (i >= 0) PREFETCH(i, 0);
        cpcommit();
        int cur = 0;
        while (i >= 0) {
            int nx = m ? (__ffsll((long long)m) - 1) : -1;
            m &= m - 1;
            cpwait0();
            __syncthreads();
            if (nx >= 0) PREFETCH(nx, cur ^ 1);
            cpcommit();

            // 8 consecutive floats (6 px + 2 halo) per row via 4x LDS.64.
            const float* pb = &patch[cur][ty * PST + xoff + tx * 6];
            ull P[3][7];
#pragma unroll
            for (int r = 0; r < 3; r++) {
                float2 d0 = *(const float2*)(pb + r * PST);
                float2 d1 = *(const float2*)(pb + r * PST + 2);
                float2 d2 = *(const float2*)(pb + r * PST + 4);
                float2 d3 = *(const float2*)(pb + r * PST + 6);
                P[r][0] = pk2(d0.x, d0.y);
                P[r][1] = pk2(d0.y, d1.x);
                P[r][2] = pk2(d1.x, d1.y);
                P[r][3] = pk2(d1.y, d2.x);
                P[r][4] = pk2(d2.x, d2.y);
                P[r][5] = pk2(d2.y, d3.x);
                P[r][6] = pk2(d3.x, d3.y);
            }

            ull cnts = cw[i];
#pragma unroll
            for (int ol = 0; ol < OG; ol++) {
                int n = (int)((cnts >> (8 * ol)) & 255);
                while (n--) { CONV_INNER(wp); wp += 10; }
            }
            cur ^= 1;
            i = nx;
        }
    }

    // Store: 3 full float2 per ol (all 8B aligned; no partial px in-tile).
    int h = h0 + ty;
    if (h < HO) {
        int wb = w0 + tx * 6;
        float* ob = out + (((size_t)(b * NOUT + og * OG)) * HO + h) * WO + wb;
#pragma unroll
        for (int ol = 0; ol < OG; ol++) {
            float2 v0, v1, v2;
            asm("mov.b64 {%0, %1}, %2;" : "=f"(v0.x), "=f"(v0.y) : "l"(acc[ol][0]));
            asm("mov.b64 {%0, %1}, %2;" : "=f"(v1.x), "=f"(v1.y) : "l"(acc[ol][1]));
            asm("mov.b64 {%0, %1}, %2;" : "=f"(v2.x), "=f"(v2.y) : "l"(acc[ol][2]));
            float* p = ob + (size_t)ol * HO * WO;
            *(float2*)p = v0;
            *(float2*)(p + 2) = v1;
            *(float2*)(p + 4) = v2;
        }
    }
}

// ---------------------------------------------------------------------------
extern "C" void kernel_launch(void* const* d_in, const int* in_sizes, int n_in,
                              void* d_out, int out_size) {
    const float* x    = (const float*)d_in[0];
    const float* w    = (const float*)d_in[1];
    const float* bias = (const float*)d_in[2];
    const int*   cin  = (const int*)d_in[3];
    const int*   cout = (const int*)d_in[4];
    int K = in_sizes[3];                       // 1024
    int B = in_sizes[0] / (NIN * HH * WW);     // 4

    prep_kernel<<<1, 1024>>>(w, cin, cout, K);

    dim3 grid(2, (HO + TROWS - 1) / TROWS, B * NG);   // (2, 12, 32)
    conv_kernel<<<grid, TH>>>(x, bias, (float*)d_out);
}